// round 1
// baseline (speedup 1.0000x reference)
#include <cuda_runtime.h>

// TPLoss: pred [4096, 8192] f32, labels [4096, 8192] i32 (0/1)
// p = sigmoid(pred); TP_b = sum(p*l); TN_b = sum((1-p)(1-l))
// Using l in {0,1}: 1 - TP - TN = 1 - N + Sp + Sl - 2*TP
// out_b = TP / (1 - TP - TN);  loss = -mean(out_b)

#define B_ROWS 4096
#define N_COLS 8192
#define VEC (N_COLS / 4)        // 2048 float4 per row
#define THREADS 256

__device__ float g_row_out[B_ROWS];   // per-row out_b scratch (no allocs allowed)

__global__ __launch_bounds__(THREADS)
void tploss_row_kernel(const float4* __restrict__ pred,
                       const int4*  __restrict__ labels) {
    const int b = blockIdx.x;
    const float4* p = pred   + (size_t)b * VEC;
    const int4*   l = labels + (size_t)b * VEC;

    float sp = 0.f;   // sum sigmoid
    float tp = 0.f;   // sum sigmoid * label
    int   cnt = 0;    // sum label

    // 2048 float4s / 256 threads = 8 iterations; fully unrolled for MLP
    #pragma unroll 8
    for (int i = threadIdx.x; i < VEC; i += THREADS) {
        float4 x = __ldg(&p[i]);
        int4   y = __ldg(&l[i]);
        float s0 = 1.f / (1.f + __expf(-x.x));
        float s1 = 1.f / (1.f + __expf(-x.y));
        float s2 = 1.f / (1.f + __expf(-x.z));
        float s3 = 1.f / (1.f + __expf(-x.w));
        sp += (s0 + s1) + (s2 + s3);
        tp += (y.x ? s0 : 0.f) + (y.y ? s1 : 0.f)
            + (y.z ? s2 : 0.f) + (y.w ? s3 : 0.f);
        cnt += y.x + y.y + y.z + y.w;
    }

    // warp reduce
    #pragma unroll
    for (int off = 16; off > 0; off >>= 1) {
        sp  += __shfl_down_sync(0xffffffffu, sp,  off);
        tp  += __shfl_down_sync(0xffffffffu, tp,  off);
        cnt += __shfl_down_sync(0xffffffffu, cnt, off);
    }

    __shared__ float s_sp[THREADS / 32];
    __shared__ float s_tp[THREADS / 32];
    __shared__ int   s_cnt[THREADS / 32];
    const int lane = threadIdx.x & 31;
    const int wid  = threadIdx.x >> 5;
    if (lane == 0) { s_sp[wid] = sp; s_tp[wid] = tp; s_cnt[wid] = cnt; }
    __syncthreads();

    if (wid == 0) {
        sp  = (lane < THREADS / 32) ? s_sp[lane]  : 0.f;
        tp  = (lane < THREADS / 32) ? s_tp[lane]  : 0.f;
        cnt = (lane < THREADS / 32) ? s_cnt[lane] : 0;
        #pragma unroll
        for (int off = 4; off > 0; off >>= 1) {
            sp  += __shfl_down_sync(0xffffffffu, sp,  off);
            tp  += __shfl_down_sync(0xffffffffu, tp,  off);
            cnt += __shfl_down_sync(0xffffffffu, cnt, off);
        }
        if (lane == 0) {
            float denom = 1.0f - (float)N_COLS + sp + (float)cnt - 2.0f * tp;
            g_row_out[b] = tp / denom;
        }
    }
}

__global__ __launch_bounds__(1024)
void tploss_final_kernel(float* __restrict__ out) {
    // 1 block, 1024 threads: each sums 4 rows, deterministic tree reduce
    float acc = 0.f;
    #pragma unroll 4
    for (int i = threadIdx.x; i < B_ROWS; i += 1024)
        acc += g_row_out[i];

    #pragma unroll
    for (int off = 16; off > 0; off >>= 1)
        acc += __shfl_down_sync(0xffffffffu, acc, off);

    __shared__ float s[32];
    const int lane = threadIdx.x & 31;
    const int wid  = threadIdx.x >> 5;
    if (lane == 0) s[wid] = acc;
    __syncthreads();
    if (wid == 0) {
        acc = s[lane];
        #pragma unroll
        for (int off = 16; off > 0; off >>= 1)
            acc += __shfl_down_sync(0xffffffffu, acc, off);
        if (lane == 0)
            out[0] = -acc / (float)B_ROWS;
    }
}

extern "C" void kernel_launch(void* const* d_in, const int* in_sizes, int n_in,
                              void* d_out, int out_size) {
    const float4* pred   = (const float4*)d_in[0];
    const int4*   labels = (const int4*)d_in[1];
    float* out = (float*)d_out;

    tploss_row_kernel<<<B_ROWS, THREADS>>>(pred, labels);
    tploss_final_kernel<<<1, 1024>>>(out);
}

// round 2
// speedup vs baseline: 1.1594x; 1.1594x over previous
#include <cuda_runtime.h>

// TPLoss: pred [4096, 8192] f32, labels [4096, 8192] i32 (0/1)
// sigmoid p; TP_b = sum(p*l); with l in {0,1}:
//   1 - TP - TN = 1 - N + Sp + Sl - 2*TP
// out_b = TP / (1 - TP - TN);  loss = -mean(out_b)
// Single fused kernel: per-row CTA + last-block final reduction.

#define B_ROWS 4096
#define N_COLS 8192
#define VEC (N_COLS / 4)        // 2048 float4 per row
#define THREADS 256

__device__ float        g_row_out[B_ROWS];
__device__ unsigned int g_done = 0;   // reset by last block each launch

// sigmoid via single MUFU: sigmoid(x) = 0.5*tanh(0.5*x) + 0.5
__device__ __forceinline__ float fast_sigmoid(float x) {
    float t;
    asm("tanh.approx.f32 %0, %1;" : "=f"(t) : "f"(x * 0.5f));
    return fmaf(t, 0.5f, 0.5f);
}

__global__ __launch_bounds__(THREADS)
void tploss_fused_kernel(const float4* __restrict__ pred,
                         const int4*  __restrict__ labels,
                         float* __restrict__ out) {
    const int b = blockIdx.x;
    const float4* p = pred   + (size_t)b * VEC;
    const int4*   l = labels + (size_t)b * VEC;

    float sp = 0.f;   // sum sigmoid
    float tp = 0.f;   // sum sigmoid * label
    int   cnt = 0;    // sum label

    #pragma unroll 8
    for (int i = threadIdx.x; i < VEC; i += THREADS) {
        float4 x = __ldcs(&p[i]);   // streaming: no reuse, don't churn L2
        int4   y = __ldcs(&l[i]);
        float s0 = fast_sigmoid(x.x);
        float s1 = fast_sigmoid(x.y);
        float s2 = fast_sigmoid(x.z);
        float s3 = fast_sigmoid(x.w);
        sp += (s0 + s1) + (s2 + s3);
        tp += (y.x ? s0 : 0.f) + (y.y ? s1 : 0.f)
            + (y.z ? s2 : 0.f) + (y.w ? s3 : 0.f);
        cnt += y.x + y.y + y.z + y.w;
    }

    // warp reduce 3 accumulators
    #pragma unroll
    for (int off = 16; off > 0; off >>= 1) {
        sp  += __shfl_down_sync(0xffffffffu, sp,  off);
        tp  += __shfl_down_sync(0xffffffffu, tp,  off);
        cnt += __shfl_down_sync(0xffffffffu, cnt, off);
    }

    __shared__ float s_sp[THREADS / 32];
    __shared__ float s_tp[THREADS / 32];
    __shared__ int   s_cnt[THREADS / 32];
    const int lane = threadIdx.x & 31;
    const int wid  = threadIdx.x >> 5;
    if (lane == 0) { s_sp[wid] = sp; s_tp[wid] = tp; s_cnt[wid] = cnt; }
    __syncthreads();

    __shared__ bool s_is_last;
    if (threadIdx.x == 0) {
        float fsp = 0.f, ftp = 0.f; int fc = 0;
        #pragma unroll
        for (int w = 0; w < THREADS / 32; w++) {
            fsp += s_sp[w]; ftp += s_tp[w]; fc += s_cnt[w];
        }
        float denom = 1.0f - (float)N_COLS + fsp + (float)fc - 2.0f * ftp;
        g_row_out[b] = ftp / denom;
        __threadfence();
        unsigned int prev = atomicAdd(&g_done, 1u);
        s_is_last = (prev == (unsigned int)(gridDim.x - 1));
    }
    __syncthreads();

    if (s_is_last) {
        __threadfence();  // acquire: make all g_row_out writes visible
        // 4096 rows / 256 threads = 16 per thread, deterministic order
        float acc = 0.f;
        #pragma unroll 16
        for (int i = threadIdx.x; i < B_ROWS; i += THREADS)
            acc += g_row_out[i];

        #pragma unroll
        for (int off = 16; off > 0; off >>= 1)
            acc += __shfl_down_sync(0xffffffffu, acc, off);

        __shared__ float s_fin[THREADS / 32];
        if (lane == 0) s_fin[wid] = acc;
        __syncthreads();
        if (threadIdx.x == 0) {
            float tot = 0.f;
            #pragma unroll
            for (int w = 0; w < THREADS / 32; w++) tot += s_fin[w];
            out[0] = -tot / (float)B_ROWS;
            g_done = 0;   // reset for next graph replay
        }
    }
}

extern "C" void kernel_launch(void* const* d_in, const int* in_sizes, int n_in,
                              void* d_out, int out_size) {
    const float4* pred   = (const float4*)d_in[0];
    const int4*   labels = (const int4*)d_in[1];
    float* out = (float*)d_out;

    tploss_fused_kernel<<<B_ROWS, THREADS>>>(pred, labels, out);
}